// round 2
// baseline (speedup 1.0000x reference)
#include <cuda_runtime.h>
#include <math.h>

#define NB 512
#define ND 512
#define EPSF 1e-6f

// ---------------- scratch (__device__ globals; no allocation allowed) ----------------
__device__ float g_n1[NB * ND];
__device__ float g_n2[NB * ND];
__device__ float g_sim[NB * NB];
__device__ float g_sim2[NB * NB];
__device__ float g_ld1[NB], g_ld2[NB];
__device__ float g_sq1[NB], g_sq2[NB];
__device__ float g_ms1[NB], g_ms2[NB];
__device__ float g_lse_row[NB], g_lse_col[NB], g_diagl[NB], g_u[NB];

// ---------------- reduction helpers ----------------
__device__ __forceinline__ float wsum(float v) {
#pragma unroll
    for (int o = 16; o; o >>= 1) v += __shfl_down_sync(0xffffffffu, v, o);
    return v;
}
__device__ __forceinline__ float wmax(float v) {
#pragma unroll
    for (int o = 16; o; o >>= 1) v = fmaxf(v, __shfl_down_sync(0xffffffffu, v, o));
    return v;
}

// ---------------- kernel 1: per-row normalize + stats ----------------
// grid = 2*NB blocks, 256 threads. Blocks [0,NB) handle (mu1, s1), rest (mu2, s2).
__global__ void prep_kernel(const float* __restrict__ mu1, const float* __restrict__ s1,
                            const float* __restrict__ mu2, const float* __restrict__ s2)
{
    __shared__ float sh[3][8];
    __shared__ float s_inv;
    const int row = blockIdx.x;
    const bool first = row < NB;
    const int r = first ? row : row - NB;
    const float* mu = (first ? mu1 : mu2) + r * ND;
    const float* sg = (first ? s1 : s2) + r * ND;
    float* nout = (first ? g_n1 : g_n2) + r * ND;
    const int t = threadIdx.x;

    float ssq = 0.f, lsum = 0.f, msum = 0.f;
    for (int c = t; c < ND; c += 256) {
        float x = mu[c];
        ssq += x * x;
        float sv = sg[c];
        lsum += __logf(sv + EPSF);
        msum += sv;
    }
    ssq = wsum(ssq); lsum = wsum(lsum); msum = wsum(msum);
    const int lane = t & 31, w = t >> 5;
    if (!lane) { sh[0][w] = ssq; sh[1][w] = lsum; sh[2][w] = msum; }
    __syncthreads();
    if (t == 0) {
        float a = 0.f, b = 0.f, c2 = 0.f;
        for (int k = 0; k < 8; k++) { a += sh[0][k]; b += sh[1][k]; c2 += sh[2][k]; }
        float inv = 1.0f / fmaxf(sqrtf(a), 1e-12f);
        s_inv = inv;
        (first ? g_ld1 : g_ld2)[r] = b;
        (first ? g_ms1 : g_ms2)[r] = c2 * (1.0f / ND);
        (first ? g_sq1 : g_sq2)[r] = a * inv * inv;   // == sum(n^2), ~1.0
    }
    __syncthreads();
    const float inv = s_inv;
    for (int c = t; c < ND; c += 256) nout[c] = mu[c] * inv;
}

// ---------------- kernel 2: the O(B^2 D) Bhattacharyya pass ----------------
#define BI 32
#define BJ 32
#define DC 32

__global__ void __launch_bounds__(256) bd_kernel(const float* __restrict__ s1g,
                                                 const float* __restrict__ s2g)
{
    // tiles stored [d][row] so the 32 tile rows for a fixed d are contiguous
    __shared__ float sn1[DC][BI + 1], ss1[DC][BI + 1];
    __shared__ float sn2[DC][BJ + 1], ss2[DC][BJ + 1];

    const int bi = blockIdx.y * BI, bj = blockIdx.x * BJ;
    const int tid = threadIdx.x;
    const int tx = tid & 15, ty = tid >> 4;    // 16x16 threads, each 2x2 outputs
    const int i0 = 2 * ty, j0 = 2 * tx;
    const int lr = tid >> 5, lc = tid & 31;    // tile loader mapping

    float t1[2][2]   = {{0.f, 0.f}, {0.f, 0.f}};
    float ldacc[2][2] = {{0.f, 0.f}, {0.f, 0.f}};
    float dot[2][2]  = {{0.f, 0.f}, {0.f, 0.f}};

    for (int dc = 0; dc < ND; dc += DC) {
#pragma unroll
        for (int k = 0; k < 4; k++) {
            const int r = k * 8 + lr;
            sn1[lc][r] = g_n1[(bi + r) * ND + dc + lc];
            ss1[lc][r] = fmaf(0.5f, s1g[(bi + r) * ND + dc + lc], 0.5f * EPSF);
            sn2[lc][r] = g_n2[(bj + r) * ND + dc + lc];
            ss2[lc][r] = fmaf(0.5f, s2g[(bj + r) * ND + dc + lc], 0.5f * EPSF);
        }
        __syncthreads();

#pragma unroll
        for (int du = 0; du < DC; du += 4) {
            // batch log over products of 4: worst case (1e-6)^4 = 1e-24 > FLT_MIN
            float prod[2][2] = {{1.f, 1.f}, {1.f, 1.f}};
#pragma unroll
            for (int dd = 0; dd < 4; dd++) {
                const int d = du + dd;
                const float a0 = sn1[d][i0], a1 = sn1[d][i0 + 1];
                const float p0 = ss1[d][i0], p1 = ss1[d][i0 + 1];
                const float b0 = sn2[d][j0], b1 = sn2[d][j0 + 1];
                const float q0 = ss2[d][j0], q1 = ss2[d][j0 + 1];
#pragma unroll
                for (int x = 0; x < 2; x++) {
                    const float a = x ? a1 : a0;
                    const float p = x ? p1 : p0;
#pragma unroll
                    for (int y = 0; y < 2; y++) {
                        const float b = y ? b1 : b0;
                        const float q = y ? q1 : q0;
                        const float s = p + q;                 // = 0.5*(s1+s2)+EPS
                        float rr;
                        asm("rcp.approx.f32 %0, %1;" : "=f"(rr) : "f"(s));
                        const float diff = a - b;
                        t1[x][y] = fmaf(diff * rr, diff, t1[x][y]);
                        prod[x][y] *= s;
                        dot[x][y] = fmaf(a, b, dot[x][y]);
                    }
                }
            }
#pragma unroll
            for (int x = 0; x < 2; x++)
#pragma unroll
                for (int y = 0; y < 2; y++)
                    ldacc[x][y] += __logf(prod[x][y]);
        }
        __syncthreads();
    }

    // epilogue: sim = exp(-bd/D), sim2 = exp(-(sq1+sq2-2*dot))
#pragma unroll
    for (int x = 0; x < 2; x++) {
        const int i = bi + i0 + x;
        const float ld1 = g_ld1[i], sq1 = g_sq1[i];
#pragma unroll
        for (int y = 0; y < 2; y++) {
            const int j = bj + j0 + y;
            const float term2 = ldacc[x][y] - 0.5f * (ld1 + g_ld2[j]);
            const float bd = fmaf(0.125f, t1[x][y], 0.5f * term2);
            g_sim[i * NB + j]  = __expf(-bd * (1.0f / ND));
            g_sim2[i * NB + j] = __expf(fmaf(2.0f, dot[x][y], -(sq1 + g_sq2[j])));
        }
    }
}

// ---------------- kernel 3: row LSE + uncertainty ----------------
// grid = NB blocks, 256 threads (each thread handles cols t and t+256)
__global__ void row_kernel(const float* __restrict__ lsp)
{
    __shared__ float shm[8], shm2[8], shs[8];
    __shared__ float s_diag, s_diag2, s_M, s_M2;
    const int i = blockIdx.x;
    const int t = threadIdx.x;
    const float scale = lsp[0];
    const float* simr = g_sim + i * NB;
    const float* sim2r = g_sim2 + i * NB;

    const float l0 = scale * simr[t],       l1 = scale * simr[t + 256];
    const float v0 = sim2r[t],              v1 = sim2r[t + 256];
    float m = fmaxf(l0, l1);
    float m2 = -1.0f;                       // sim2 > 0 always
    if (t == i)       { s_diag = l0; s_diag2 = v0; } else m2 = v0;
    if (t + 256 == i) { s_diag = l1; s_diag2 = v1; } else m2 = fmaxf(m2, v1);

    m = wmax(m); m2 = wmax(m2);
    const int lane = t & 31, w = t >> 5;
    if (!lane) { shm[w] = m; shm2[w] = m2; }
    __syncthreads();
    if (t == 0) {
        float M = shm[0], M2 = shm2[0];
        for (int k = 1; k < 8; k++) { M = fmaxf(M, shm[k]); M2 = fmaxf(M2, shm2[k]); }
        s_M = M; s_M2 = M2;
    }
    __syncthreads();
    const float M = s_M;
    float su = __expf(l0 - M) + __expf(l1 - M);
    su = wsum(su);
    if (!lane) shs[w] = su;
    __syncthreads();
    if (t == 0) {
        float S = 0.f;
        for (int k = 0; k < 8; k++) S += shs[k];
        g_lse_row[i] = M + __logf(S);
        g_diagl[i]   = s_diag;
        g_u[i]       = __expf(-s_diag2 / s_M2);
    }
}

// ---------------- kernel 4: column LSE (online softmax, coalesced) ----------------
// grid = NB/32 blocks, 256 threads: x = col-in-group, y = row-stripe
__global__ void col_kernel(const float* __restrict__ lsp)
{
    __shared__ float sm[8][32], ss[8][32];
    const float scale = lsp[0];
    const int x = threadIdx.x & 31, y = threadIdx.x >> 5;
    const int j = blockIdx.x * 32 + x;
    float m = -1e30f, s = 0.0f;
    for (int r = y; r < NB; r += 8) {
        const float l = scale * g_sim[r * NB + j];
        const float nm = fmaxf(m, l);
        s = s * __expf(m - nm) + __expf(l - nm);
        m = nm;
    }
    sm[y][x] = m; ss[y][x] = s;
    __syncthreads();
    if (y == 0) {
        float M = m;
        for (int k = 1; k < 8; k++) M = fmaxf(M, sm[k][x]);
        float S = 0.f;
        for (int k = 0; k < 8; k++) S += ss[k][x] * __expf(sm[k][x] - M);
        g_lse_col[j] = M + __logf(S);
    }
}

// ---------------- kernel 5: final scalar reductions ----------------
__global__ void final_kernel(float* __restrict__ out)
{
    __shared__ float sh[6][16];
    const int t = threadIdx.x;   // 512 threads
    const float ce_r = g_lse_row[t] - g_diagl[t];
    const float ce_c = g_lse_col[t] - g_diagl[t];
    const float u = g_u[t];
    const float as = 0.5f * (g_ms1[t] + g_ms2[t]);
    float v[6] = { ce_r, ce_c, u, u * u, as * as, u * as };
    const int lane = t & 31, w = t >> 5;
#pragma unroll
    for (int k = 0; k < 6; k++) {
        const float r = wsum(v[k]);
        if (!lane) sh[k][w] = r;
    }
    __syncthreads();
    if (t == 0) {
        float s[6];
        for (int k = 0; k < 6; k++) {
            float a = 0.f;
            for (int q = 0; q < 16; q++) a += sh[k][q];
            s[k] = a;
        }
        const float loss_pro = 0.5f * ((s[0] + s[1]) * (1.0f / NB));
        const float cosv = s[5] / (fmaxf(sqrtf(s[3]), 1e-12f) * fmaxf(sqrtf(s[4]), 1e-12f));
        out[0] = loss_pro;
        out[1] = 2.4f * (1.0f - cosv);
        out[2] = 0.5f * (s[2] * (1.0f / NB));
    }
}

// ---------------- launch ----------------
extern "C" void kernel_launch(void* const* d_in, const int* in_sizes, int n_in,
                              void* d_out, int out_size)
{
    const float* mu1 = (const float*)d_in[0];
    const float* s1  = (const float*)d_in[1];
    const float* mu2 = (const float*)d_in[2];
    const float* s2  = (const float*)d_in[3];
    const float* ls  = (const float*)d_in[4];
    float* out = (float*)d_out;

    prep_kernel<<<2 * NB, 256>>>(mu1, s1, mu2, s2);
    dim3 grid(NB / BJ, NB / BI);
    bd_kernel<<<grid, 256>>>(s1, s2);
    row_kernel<<<NB, 256>>>(ls);
    col_kernel<<<NB / 32, 256>>>(ls);
    final_kernel<<<1, NB>>>(out);
}

// round 3
// speedup vs baseline: 1.2536x; 1.2536x over previous
#include <cuda_runtime.h>
#include <math.h>

#define NB 512
#define ND 512
#define EPSF 1e-6f
#define HEPS (0.5f*1e-6f)

typedef unsigned long long u64t;

// ---------------- f32x2 packed helpers (sm_100a) ----------------
__device__ __forceinline__ u64t pk2(float lo, float hi){ u64t r; asm("mov.b64 %0, {%1,%2};" : "=l"(r) : "f"(lo), "f"(hi)); return r; }
__device__ __forceinline__ void upk2(u64t v, float&lo, float&hi){ asm("mov.b64 {%0,%1}, %2;" : "=f"(lo), "=f"(hi) : "l"(v)); }
__device__ __forceinline__ u64t fma2_(u64t a,u64t b,u64t c){ u64t d; asm("fma.rn.f32x2 %0,%1,%2,%3;" : "=l"(d) : "l"(a),"l"(b),"l"(c)); return d; }
__device__ __forceinline__ u64t mul2_(u64t a,u64t b){ u64t d; asm("mul.rn.f32x2 %0,%1,%2;" : "=l"(d) : "l"(a),"l"(b)); return d; }
__device__ __forceinline__ u64t add2_(u64t a,u64t b){ u64t d; asm("add.rn.f32x2 %0,%1,%2;" : "=l"(d) : "l"(a),"l"(b)); return d; }
__device__ __forceinline__ float rcpa(float x){ float r; asm("rcp.approx.f32 %0, %1;" : "=f"(r) : "f"(x)); return r; }
__device__ __forceinline__ float lg2a(float x){ float r; asm("lg2.approx.f32 %0, %1;" : "=f"(r) : "f"(x)); return r; }

// ---------------- scratch ----------------
__device__ float g_n1[NB * ND];
__device__ float g_n2[NB * ND];   // holds NEGATED normalized mu2
__device__ float g_sim[NB * NB];
__device__ float g_sim2[NB * NB];
__device__ float g_ld1[NB], g_ld2[NB];
__device__ float g_ms1[NB], g_ms2[NB];
__device__ float g_lse_row[NB], g_diagl[NB], g_u[NB];
__device__ float g_cm[16 * NB], g_cs[16 * NB];

// ---------------- reduction helpers ----------------
__device__ __forceinline__ float wsum(float v) {
#pragma unroll
    for (int o = 16; o; o >>= 1) v += __shfl_down_sync(0xffffffffu, v, o);
    return v;
}
__device__ __forceinline__ float wmax(float v) {
#pragma unroll
    for (int o = 16; o; o >>= 1) v = fmaxf(v, __shfl_down_sync(0xffffffffu, v, o));
    return v;
}

// ---------------- kernel 1: per-row normalize + stats ----------------
__global__ void prep_kernel(const float* __restrict__ mu1, const float* __restrict__ s1,
                            const float* __restrict__ mu2, const float* __restrict__ s2)
{
    __shared__ float sh[3][8];
    __shared__ float s_inv;
    const int row = blockIdx.x;
    const bool first = row < NB;
    const int r = first ? row : row - NB;
    const float* mu = (first ? mu1 : mu2) + r * ND;
    const float* sg = (first ? s1 : s2) + r * ND;
    float* nout = (first ? g_n1 : g_n2) + r * ND;
    const int t = threadIdx.x;

    float ssq = 0.f, lsum = 0.f, msum = 0.f;
    for (int c = t; c < ND; c += 256) {
        float x = mu[c];
        ssq += x * x;
        float sv = sg[c];
        lsum += __logf(sv + EPSF);
        msum += sv;
    }
    ssq = wsum(ssq); lsum = wsum(lsum); msum = wsum(msum);
    const int lane = t & 31, w = t >> 5;
    if (!lane) { sh[0][w] = ssq; sh[1][w] = lsum; sh[2][w] = msum; }
    __syncthreads();
    if (t == 0) {
        float a = 0.f, b = 0.f, c2 = 0.f;
        for (int k = 0; k < 8; k++) { a += sh[0][k]; b += sh[1][k]; c2 += sh[2][k]; }
        float inv = 1.0f / fmaxf(sqrtf(a), 1e-12f);
        s_inv = first ? inv : -inv;          // negate n2 once here
        (first ? g_ld1 : g_ld2)[r] = b;
        (first ? g_ms1 : g_ms2)[r] = c2 * (1.0f / ND);
    }
    __syncthreads();
    const float inv = s_inv;
    for (int c = t; c < ND; c += 256) nout[c] = mu[c] * inv;
}

// ---------------- kernel 2: Bhattacharyya O(B^2 D) pass (f32x2 + batch inversion) ----------------
// 32x32 output tile, 64 threads, each thread 4x4 outputs (j packed as 2x f32x2).
__global__ void __launch_bounds__(64) bd_kernel(const float* __restrict__ s1g,
                                                const float* __restrict__ s2g)
{
    __shared__ __align__(16) float sn1[32][36], ss1[32][36];   // [row i][d], float4-readable
    __shared__ __align__(16) float sn2[32][34], ss2[32][34];   // [d][row j], f32x2-readable

    const int bi = blockIdx.y * 32, bj = blockIdx.x * 32;
    const int tid = threadIdx.x;
    const int tx = tid & 7, ty = tid >> 3;
    const int i0 = ty * 4, j0 = tx * 4;
    const int lc = tid & 31, lw = tid >> 5;

    u64t t1a[4][2], d2a[4][2], lda[4][2];
#pragma unroll
    for (int x = 0; x < 4; x++)
#pragma unroll
        for (int y = 0; y < 2; y++) { t1a[x][y] = 0ull; d2a[x][y] = 0ull; lda[x][y] = 0ull; }

    for (int dc = 0; dc < ND; dc += 32) {
#pragma unroll
        for (int k = 0; k < 16; k++) {
            const int r = lw * 16 + k;
            sn1[r][lc] = g_n1[(bi + r) * ND + dc + lc];
            ss1[r][lc] = fmaf(0.5f, s1g[(bi + r) * ND + dc + lc], HEPS);
            sn2[lc][r] = g_n2[(bj + r) * ND + dc + lc];           // already negated
            ss2[lc][r] = fmaf(0.5f, s2g[(bj + r) * ND + dc + lc], HEPS);
        }
        __syncthreads();

#pragma unroll 2
        for (int dg = 0; dg < 32; dg += 4) {
            u64t bn[2][4], q[2][4];
#pragma unroll
            for (int dd = 0; dd < 4; dd++) {
#pragma unroll
                for (int yp = 0; yp < 2; yp++) {
                    bn[yp][dd] = *(const u64t*)&sn2[dg + dd][j0 + 2 * yp];
                    q[yp][dd]  = *(const u64t*)&ss2[dg + dd][j0 + 2 * yp];
                }
            }
#pragma unroll
            for (int x = 0; x < 4; x++) {
                const float4 av = *(const float4*)&sn1[i0 + x][dg];
                const float4 pv = *(const float4*)&ss1[i0 + x][dg];
                u64t a2[4], p2[4];
                a2[0] = pk2(av.x, av.x); a2[1] = pk2(av.y, av.y);
                a2[2] = pk2(av.z, av.z); a2[3] = pk2(av.w, av.w);
                p2[0] = pk2(pv.x, pv.x); p2[1] = pk2(pv.y, pv.y);
                p2[2] = pk2(pv.z, pv.z); p2[3] = pk2(pv.w, pv.w);
#pragma unroll
                for (int yp = 0; yp < 2; yp++) {
                    const u64t s0 = add2_(p2[0], q[yp][0]);
                    const u64t s1_ = add2_(p2[1], q[yp][1]);
                    const u64t s2_ = add2_(p2[2], q[yp][2]);
                    const u64t s3_ = add2_(p2[3], q[yp][3]);
                    const u64t df0 = add2_(a2[0], bn[yp][0]);   // a - b (b stored negated)
                    const u64t df1 = add2_(a2[1], bn[yp][1]);
                    const u64t df2 = add2_(a2[2], bn[yp][2]);
                    const u64t df3 = add2_(a2[3], bn[yp][3]);
                    d2a[x][yp] = fma2_(df0, df0, d2a[x][yp]);
                    d2a[x][yp] = fma2_(df1, df1, d2a[x][yp]);
                    d2a[x][yp] = fma2_(df2, df2, d2a[x][yp]);
                    d2a[x][yp] = fma2_(df3, df3, d2a[x][yp]);
                    // batched product for log + Montgomery batch inversion
                    const u64t p01  = mul2_(s0, s1_);
                    const u64t p012 = mul2_(p01, s2_);
                    const u64t P    = mul2_(p012, s3_);
                    float Pl, Ph; upk2(P, Pl, Ph);
                    lda[x][yp] = add2_(lda[x][yp], pk2(lg2a(Pl), lg2a(Ph)));
                    const u64t r2   = pk2(rcpa(Pl), rcpa(Ph));
                    const u64t inv3 = mul2_(r2, p012);
                    const u64t r3   = mul2_(r2, s3_);
                    const u64t inv2 = mul2_(r3, p01);
                    const u64t r23  = mul2_(r3, s2_);
                    const u64t inv1 = mul2_(r23, s0);
                    const u64t inv0 = mul2_(r23, s1_);
                    t1a[x][yp] = fma2_(mul2_(df0, inv0), df0, t1a[x][yp]);
                    t1a[x][yp] = fma2_(mul2_(df1, inv1), df1, t1a[x][yp]);
                    t1a[x][yp] = fma2_(mul2_(df2, inv2), df2, t1a[x][yp]);
                    t1a[x][yp] = fma2_(mul2_(df3, inv3), df3, t1a[x][yp]);
                }
            }
        }
        __syncthreads();
    }

    // epilogue: sim = exp(-bd/D), sim2 = exp(-||n1-n2||^2)
#pragma unroll
    for (int x = 0; x < 4; x++) {
        const int i = bi + i0 + x;
        const float ld1v = g_ld1[i];
        float so[4], s2o[4];
#pragma unroll
        for (int yp = 0; yp < 2; yp++) {
            float tA, tB, dA, dB, lA, lB;
            upk2(t1a[x][yp], tA, tB);
            upk2(d2a[x][yp], dA, dB);
            upk2(lda[x][yp], lA, lB);
            const int j = bj + j0 + 2 * yp;
            const float t2A = lA * (float)M_LN2 - 0.5f * (ld1v + g_ld2[j]);
            const float t2B = lB * (float)M_LN2 - 0.5f * (ld1v + g_ld2[j + 1]);
            const float bdA = fmaf(0.125f, tA, 0.5f * t2A);
            const float bdB = fmaf(0.125f, tB, 0.5f * t2B);
            so[2 * yp]     = __expf(-bdA * (1.0f / ND));
            so[2 * yp + 1] = __expf(-bdB * (1.0f / ND));
            s2o[2 * yp]     = __expf(-dA);
            s2o[2 * yp + 1] = __expf(-dB);
        }
        *(float4*)&g_sim[i * NB + bj + j0]  = make_float4(so[0], so[1], so[2], so[3]);
        *(float4*)&g_sim2[i * NB + bj + j0] = make_float4(s2o[0], s2o[1], s2o[2], s2o[3]);
    }
}

// ---------------- kernel 3: row LSE + uncertainty ----------------
__global__ void row_kernel(const float* __restrict__ lsp)
{
    __shared__ float shm[8], shm2[8], shs[8];
    __shared__ float s_diag, s_diag2, s_M, s_M2;
    const int i = blockIdx.x;
    const int t = threadIdx.x;
    const float scale = lsp[0];
    const float* simr = g_sim + i * NB;
    const float* sim2r = g_sim2 + i * NB;

    const float l0 = scale * simr[t], l1 = scale * simr[t + 256];
    const float v0 = sim2r[t],        v1 = sim2r[t + 256];
    float m = fmaxf(l0, l1);
    float m2 = -1.0f;
    if (t == i)       { s_diag = l0; s_diag2 = v0; } else m2 = v0;
    if (t + 256 == i) { s_diag = l1; s_diag2 = v1; } else m2 = fmaxf(m2, v1);

    m = wmax(m); m2 = wmax(m2);
    const int lane = t & 31, w = t >> 5;
    if (!lane) { shm[w] = m; shm2[w] = m2; }
    __syncthreads();
    if (t == 0) {
        float M = shm[0], M2 = shm2[0];
        for (int k = 1; k < 8; k++) { M = fmaxf(M, shm[k]); M2 = fmaxf(M2, shm2[k]); }
        s_M = M; s_M2 = M2;
    }
    __syncthreads();
    const float M = s_M;
    float su = __expf(l0 - M) + __expf(l1 - M);
    su = wsum(su);
    if (!lane) shs[w] = su;
    __syncthreads();
    if (t == 0) {
        float S = 0.f;
        for (int k = 0; k < 8; k++) S += shs[k];
        g_lse_row[i] = M + __logf(S);
        g_diagl[i]   = s_diag;
        g_u[i]       = __expf(-s_diag2 / s_M2);
    }
}

// ---------------- kernel 4: column LSE partials (256 blocks) ----------------
__global__ void colpart_kernel(const float* __restrict__ lsp)
{
    __shared__ float sm[8][32], ssp[8][32];
    const float scale = lsp[0];
    const int x = threadIdx.x & 31, y = threadIdx.x >> 5;
    const int j = blockIdx.x * 32 + x;
    const int r0 = blockIdx.y * 32 + y * 4;
    float m = -1e30f, s = 0.0f;
#pragma unroll
    for (int k = 0; k < 4; k++) {
        const float l = scale * g_sim[(r0 + k) * NB + j];
        const float nm = fmaxf(m, l);
        s = s * __expf(m - nm) + __expf(l - nm);
        m = nm;
    }
    sm[y][x] = m; ssp[y][x] = s;
    __syncthreads();
    if (y == 0) {
        float M = m;
#pragma unroll
        for (int k = 1; k < 8; k++) M = fmaxf(M, sm[k][x]);
        float S = 0.f;
#pragma unroll
        for (int k = 0; k < 8; k++) S += ssp[k][x] * __expf(sm[k][x] - M);
        g_cm[blockIdx.y * NB + j] = M;
        g_cs[blockIdx.y * NB + j] = S;
    }
}

// ---------------- kernel 5: final reductions (incl. column LSE combine) ----------------
__global__ void final_kernel(float* __restrict__ out)
{
    __shared__ float sh[6][16];
    const int t = threadIdx.x;   // 512 threads
    float M = -1e30f;
#pragma unroll
    for (int k = 0; k < 16; k++) M = fmaxf(M, g_cm[k * NB + t]);
    float S = 0.f;
#pragma unroll
    for (int k = 0; k < 16; k++) S += g_cs[k * NB + t] * __expf(g_cm[k * NB + t] - M);
    const float lse_col = M + __logf(S);

    const float diag = g_diagl[t];
    const float ce_r = g_lse_row[t] - diag;
    const float ce_c = lse_col - diag;
    const float u = g_u[t];
    const float as = 0.5f * (g_ms1[t] + g_ms2[t]);
    float v[6] = { ce_r, ce_c, u, u * u, as * as, u * as };
    const int lane = t & 31, w = t >> 5;
#pragma unroll
    for (int k = 0; k < 6; k++) {
        const float r = wsum(v[k]);
        if (!lane) sh[k][w] = r;
    }
    __syncthreads();
    if (t == 0) {
        float s[6];
        for (int k = 0; k < 6; k++) {
            float a = 0.f;
            for (int q = 0; q < 16; q++) a += sh[k][q];
            s[k] = a;
        }
        const float loss_pro = 0.5f * ((s[0] + s[1]) * (1.0f / NB));
        const float cosv = s[5] / (fmaxf(sqrtf(s[3]), 1e-12f) * fmaxf(sqrtf(s[4]), 1e-12f));
        out[0] = loss_pro;
        out[1] = 2.4f * (1.0f - cosv);
        out[2] = 0.5f * (s[2] * (1.0f / NB));
    }
}

// ---------------- launch ----------------
extern "C" void kernel_launch(void* const* d_in, const int* in_sizes, int n_in,
                              void* d_out, int out_size)
{
    const float* mu1 = (const float*)d_in[0];
    const float* s1  = (const float*)d_in[1];
    const float* mu2 = (const float*)d_in[2];
    const float* s2  = (const float*)d_in[3];
    const float* ls  = (const float*)d_in[4];
    float* out = (float*)d_out;

    prep_kernel<<<2 * NB, 256>>>(mu1, s1, mu2, s2);
    dim3 grid(NB / 32, NB / 32);
    bd_kernel<<<grid, 64>>>(s1, s2);
    row_kernel<<<NB, 256>>>(ls);
    colpart_kernel<<<dim3(NB / 32, NB / 32), 256>>>(ls);
    final_kernel<<<1, NB>>>(out);
}

// round 5
// speedup vs baseline: 1.4648x; 1.1684x over previous
#include <cuda_runtime.h>
#include <math.h>

#define NB 512
#define ND 512
#define EPSF 1e-6f
#define HEPS (0.5f*1e-6f)

typedef unsigned long long u64t;

// ---------------- f32x2 packed helpers (sm_100a) ----------------
__device__ __forceinline__ u64t pk2(float lo, float hi){ u64t r; asm("mov.b64 %0, {%1,%2};" : "=l"(r) : "f"(lo), "f"(hi)); return r; }
__device__ __forceinline__ void upk2(u64t v, float&lo, float&hi){ asm("mov.b64 {%0,%1}, %2;" : "=f"(lo), "=f"(hi) : "l"(v)); }
__device__ __forceinline__ u64t fma2_(u64t a,u64t b,u64t c){ u64t d; asm("fma.rn.f32x2 %0,%1,%2,%3;" : "=l"(d) : "l"(a),"l"(b),"l"(c)); return d; }
__device__ __forceinline__ u64t mul2_(u64t a,u64t b){ u64t d; asm("mul.rn.f32x2 %0,%1,%2;" : "=l"(d) : "l"(a),"l"(b)); return d; }
__device__ __forceinline__ u64t add2_(u64t a,u64t b){ u64t d; asm("add.rn.f32x2 %0,%1,%2;" : "=l"(d) : "l"(a),"l"(b)); return d; }
__device__ __forceinline__ float rcpa(float x){ float r; asm("rcp.approx.f32 %0, %1;" : "=f"(r) : "f"(x)); return r; }
__device__ __forceinline__ float lg2a(float x){ float r; asm("lg2.approx.f32 %0, %1;" : "=f"(r) : "f"(x)); return r; }

// ---------------- scratch ----------------
__device__ float g_n1[NB * ND];
__device__ float g_n2[NB * ND];   // holds NEGATED normalized mu2
__device__ float g_sim[NB * NB];
__device__ float g_sim2[NB * NB];
__device__ float g_ld1[NB], g_ld2[NB];
__device__ float g_ms1[NB], g_ms2[NB];
__device__ float g_lse_row[NB], g_diagl[NB], g_u[NB];
__device__ float g_cm[16 * NB], g_cs[16 * NB];

// ---------------- reduction helpers ----------------
__device__ __forceinline__ float wsum(float v) {
#pragma unroll
    for (int o = 16; o; o >>= 1) v += __shfl_down_sync(0xffffffffu, v, o);
    return v;
}
__device__ __forceinline__ float wmax(float v) {
#pragma unroll
    for (int o = 16; o; o >>= 1) v = fmaxf(v, __shfl_down_sync(0xffffffffu, v, o));
    return v;
}

// ---------------- kernel 1: per-row normalize + stats ----------------
__global__ void prep_kernel(const float* __restrict__ mu1, const float* __restrict__ s1,
                            const float* __restrict__ mu2, const float* __restrict__ s2)
{
    __shared__ float sh[3][8];
    __shared__ float s_inv;
    const int row = blockIdx.x;
    const bool first = row < NB;
    const int r = first ? row : row - NB;
    const float* mu = (first ? mu1 : mu2) + r * ND;
    const float* sg = (first ? s1 : s2) + r * ND;
    float* nout = (first ? g_n1 : g_n2) + r * ND;
    const int t = threadIdx.x;

    float ssq = 0.f, lsum = 0.f, msum = 0.f;
    for (int c = t; c < ND; c += 256) {
        float x = mu[c];
        ssq += x * x;
        float sv = sg[c];
        lsum += __logf(sv + EPSF);
        msum += sv;
    }
    ssq = wsum(ssq); lsum = wsum(lsum); msum = wsum(msum);
    const int lane = t & 31, w = t >> 5;
    if (!lane) { sh[0][w] = ssq; sh[1][w] = lsum; sh[2][w] = msum; }
    __syncthreads();
    if (t == 0) {
        float a = 0.f, b = 0.f, c2 = 0.f;
        for (int k = 0; k < 8; k++) { a += sh[0][k]; b += sh[1][k]; c2 += sh[2][k]; }
        float inv = 1.0f / fmaxf(sqrtf(a), 1e-12f);
        s_inv = first ? inv : -inv;          // negate n2 once here
        (first ? g_ld1 : g_ld2)[r] = b;
        (first ? g_ms1 : g_ms2)[r] = c2 * (1.0f / ND);
    }
    __syncthreads();
    const float inv = s_inv;
    for (int c = t; c < ND; c += 256) nout[c] = mu[c] * inv;
}

// ---------------- kernel 2: Bhattacharyya O(B^2 D) pass ----------------
// 32x32 output tile, 128 threads = 2 decoupled 64-thread groups splitting D.
// Each group has private smem buffers + a private named barrier, so one group's
// global-load phase overlaps the other group's compute phase.
__global__ void __launch_bounds__(128) bd_kernel(const float* __restrict__ s1g,
                                                 const float* __restrict__ s2g)
{
    __shared__ __align__(16) float sn1[2][32][36], ss1[2][32][36];   // [grp][row i][d]
    __shared__ __align__(16) float sn2[2][32][34], ss2[2][32][34];   // [grp][d][row j]
    __shared__ u64t comb[64][24];                                    // group-1 partials

    const int bi = blockIdx.y * 32, bj = blockIdx.x * 32;
    const int tid = threadIdx.x;
    const int g  = tid >> 6;          // group id 0/1
    const int t  = tid & 63;          // thread-in-group
    const int tx = t & 7, ty = t >> 3;
    const int i0 = ty * 4, j0 = tx * 4;
    const int lc = t & 31, lw = t >> 5;

    u64t t1a[4][2], d2a[4][2], lda[4][2];
#pragma unroll
    for (int x = 0; x < 4; x++)
#pragma unroll
        for (int y = 0; y < 2; y++) { t1a[x][y] = 0ull; d2a[x][y] = 0ull; lda[x][y] = 0ull; }

    for (int dc = g * 32; dc < ND; dc += 64) {
#pragma unroll
        for (int k = 0; k < 16; k++) {
            const int r = lw * 16 + k;
            sn1[g][r][lc] = g_n1[(bi + r) * ND + dc + lc];
            ss1[g][r][lc] = fmaf(0.5f, s1g[(bi + r) * ND + dc + lc], HEPS);
            sn2[g][lc][r] = g_n2[(bj + r) * ND + dc + lc];           // already negated
            ss2[g][lc][r] = fmaf(0.5f, s2g[(bj + r) * ND + dc + lc], HEPS);
        }
        asm volatile("bar.sync %0, 64;" :: "r"(g + 1) : "memory");

#pragma unroll 2
        for (int dg = 0; dg < 32; dg += 4) {
            u64t bn[2][4], q[2][4];
#pragma unroll
            for (int dd = 0; dd < 4; dd++) {
#pragma unroll
                for (int yp = 0; yp < 2; yp++) {
                    bn[yp][dd] = *(const u64t*)&sn2[g][dg + dd][j0 + 2 * yp];
                    q[yp][dd]  = *(const u64t*)&ss2[g][dg + dd][j0 + 2 * yp];
                }
            }
#pragma unroll
            for (int x = 0; x < 4; x++) {
                const float4 av = *(const float4*)&sn1[g][i0 + x][dg];
                const float4 pv = *(const float4*)&ss1[g][i0 + x][dg];
                u64t a2[4], p2[4];
                a2[0] = pk2(av.x, av.x); a2[1] = pk2(av.y, av.y);
                a2[2] = pk2(av.z, av.z); a2[3] = pk2(av.w, av.w);
                p2[0] = pk2(pv.x, pv.x); p2[1] = pk2(pv.y, pv.y);
                p2[2] = pk2(pv.z, pv.z); p2[3] = pk2(pv.w, pv.w);
#pragma unroll
                for (int yp = 0; yp < 2; yp++) {
                    const u64t s0  = add2_(p2[0], q[yp][0]);
                    const u64t s1_ = add2_(p2[1], q[yp][1]);
                    const u64t s2_ = add2_(p2[2], q[yp][2]);
                    const u64t s3_ = add2_(p2[3], q[yp][3]);
                    const u64t df0 = add2_(a2[0], bn[yp][0]);   // a - b (b stored negated)
                    const u64t df1 = add2_(a2[1], bn[yp][1]);
                    const u64t df2 = add2_(a2[2], bn[yp][2]);
                    const u64t df3 = add2_(a2[3], bn[yp][3]);
                    d2a[x][yp] = fma2_(df0, df0, d2a[x][yp]);
                    d2a[x][yp] = fma2_(df1, df1, d2a[x][yp]);
                    d2a[x][yp] = fma2_(df2, df2, d2a[x][yp]);
                    d2a[x][yp] = fma2_(df3, df3, d2a[x][yp]);
                    // batched product for log + Montgomery batch inversion
                    const u64t p01  = mul2_(s0, s1_);
                    const u64t p012 = mul2_(p01, s2_);
                    const u64t P    = mul2_(p012, s3_);
                    float Pl, Ph; upk2(P, Pl, Ph);
                    lda[x][yp] = add2_(lda[x][yp], pk2(lg2a(Pl), lg2a(Ph)));
                    const u64t r2   = pk2(rcpa(Pl), rcpa(Ph));
                    const u64t inv3 = mul2_(r2, p012);
                    const u64t r3   = mul2_(r2, s3_);
                    const u64t inv2 = mul2_(r3, p01);
                    const u64t r23  = mul2_(r3, s2_);
                    const u64t inv1 = mul2_(r23, s0);
                    const u64t inv0 = mul2_(r23, s1_);
                    t1a[x][yp] = fma2_(mul2_(df0, inv0), df0, t1a[x][yp]);
                    t1a[x][yp] = fma2_(mul2_(df1, inv1), df1, t1a[x][yp]);
                    t1a[x][yp] = fma2_(mul2_(df2, inv2), df2, t1a[x][yp]);
                    t1a[x][yp] = fma2_(mul2_(df3, inv3), df3, t1a[x][yp]);
                }
            }
        }
        asm volatile("bar.sync %0, 64;" :: "r"(g + 1) : "memory");
    }

    // ---- combine group partials: group 1 -> smem, group 0 adds + epilogue ----
    if (g == 1) {
        int idx = 0;
#pragma unroll
        for (int x = 0; x < 4; x++)
#pragma unroll
            for (int yp = 0; yp < 2; yp++) {
                comb[t][idx++] = t1a[x][yp];
                comb[t][idx++] = d2a[x][yp];
                comb[t][idx++] = lda[x][yp];
            }
    }
    __syncthreads();
    if (g == 0) {
        int idx = 0;
#pragma unroll
        for (int x = 0; x < 4; x++)
#pragma unroll
            for (int yp = 0; yp < 2; yp++) {
                t1a[x][yp] = add2_(t1a[x][yp], comb[t][idx++]);
                d2a[x][yp] = add2_(d2a[x][yp], comb[t][idx++]);
                lda[x][yp] = add2_(lda[x][yp], comb[t][idx++]);
            }
        // epilogue: sim = exp(-bd/D), sim2 = exp(-||n1-n2||^2)
#pragma unroll
        for (int x = 0; x < 4; x++) {
            const int i = bi + i0 + x;
            const float ld1v = g_ld1[i];
            float so[4], s2o[4];
#pragma unroll
            for (int yp = 0; yp < 2; yp++) {
                float tA, tB, dA, dB, lA, lB;
                upk2(t1a[x][yp], tA, tB);
                upk2(d2a[x][yp], dA, dB);
                upk2(lda[x][yp], lA, lB);
                const int j = bj + j0 + 2 * yp;
                const float t2A = lA * (float)M_LN2 - 0.5f * (ld1v + g_ld2[j]);
                const float t2B = lB * (float)M_LN2 - 0.5f * (ld1v + g_ld2[j + 1]);
                const float bdA = fmaf(0.125f, tA, 0.5f * t2A);
                const float bdB = fmaf(0.125f, tB, 0.5f * t2B);
                so[2 * yp]      = __expf(-bdA * (1.0f / ND));
                so[2 * yp + 1]  = __expf(-bdB * (1.0f / ND));
                s2o[2 * yp]     = __expf(-dA);
                s2o[2 * yp + 1] = __expf(-dB);
            }
            *(float4*)&g_sim[i * NB + bj + j0]  = make_float4(so[0], so[1], so[2], so[3]);
            *(float4*)&g_sim2[i * NB + bj + j0] = make_float4(s2o[0], s2o[1], s2o[2], s2o[3]);
        }
    }
}

// ---------------- kernel 3: fused row LSE + column LSE partials ----------------
// blocks [0,NB): per-row LSE + uncertainty.  blocks [NB, NB+256): column partials.
__global__ void rowcol_kernel(const float* __restrict__ lsp)
{
    const float scale = lsp[0];
    const int t = threadIdx.x;
    const int lane = t & 31, w = t >> 5;

    if (blockIdx.x < NB) {
        __shared__ float shm[8], shm2[8], shs[8];
        __shared__ float s_diag, s_diag2, s_M, s_M2;
        const int i = blockIdx.x;
        const float* simr = g_sim + i * NB;
        const float* sim2r = g_sim2 + i * NB;

        const float l0 = scale * simr[t], l1 = scale * simr[t + 256];
        const float v0 = sim2r[t],        v1 = sim2r[t + 256];
        float m = fmaxf(l0, l1);
        float m2 = -1.0f;
        if (t == i)       { s_diag = l0; s_diag2 = v0; } else m2 = v0;
        if (t + 256 == i) { s_diag = l1; s_diag2 = v1; } else m2 = fmaxf(m2, v1);

        m = wmax(m); m2 = wmax(m2);
        if (!lane) { shm[w] = m; shm2[w] = m2; }
        __syncthreads();
        if (t == 0) {
            float M = shm[0], M2 = shm2[0];
            for (int k = 1; k < 8; k++) { M = fmaxf(M, shm[k]); M2 = fmaxf(M2, shm2[k]); }
            s_M = M; s_M2 = M2;
        }
        __syncthreads();
        const float M = s_M;
        float su = __expf(l0 - M) + __expf(l1 - M);
        su = wsum(su);
        if (!lane) shs[w] = su;
        __syncthreads();
        if (t == 0) {
            float S = 0.f;
            for (int k = 0; k < 8; k++) S += shs[k];
            g_lse_row[i] = M + __logf(S);
            g_diagl[i]   = s_diag;
            g_u[i]       = __expf(-s_diag2 / s_M2);
        }
    } else {
        __shared__ float sm[8][32], ssp[8][32];
        const int bid = blockIdx.x - NB;
        const int jg = bid & 15, rg = bid >> 4;
        const int x = t & 31, y = t >> 5;
        const int j = jg * 32 + x;
        const int r0 = rg * 32 + y * 4;
        float m = -1e30f, s = 0.0f;
#pragma unroll
        for (int k = 0; k < 4; k++) {
            const float l = scale * g_sim[(r0 + k) * NB + j];
            const float nm = fmaxf(m, l);
            s = s * __expf(m - nm) + __expf(l - nm);
            m = nm;
        }
        sm[y][x] = m; ssp[y][x] = s;
        __syncthreads();
        if (y == 0) {
            float M = m;
#pragma unroll
            for (int k = 1; k < 8; k++) M = fmaxf(M, sm[k][x]);
            float S = 0.f;
#pragma unroll
            for (int k = 0; k < 8; k++) S += ssp[k][x] * __expf(sm[k][x] - M);
            g_cm[rg * NB + j] = M;
            g_cs[rg * NB + j] = S;
        }
    }
}

// ---------------- kernel 4: final reductions (incl. column LSE combine) ----------------
__global__ void final_kernel(float* __restrict__ out)
{
    __shared__ float sh[6][16];
    const int t = threadIdx.x;   // 512 threads
    float M = -1e30f;
#pragma unroll
    for (int k = 0; k < 16; k++) M = fmaxf(M, g_cm[k * NB + t]);
    float S = 0.f;
#pragma unroll
    for (int k = 0; k < 16; k++) S += g_cs[k * NB + t] * __expf(g_cm[k * NB + t] - M);
    const float lse_col = M + __logf(S);

    const float diag = g_diagl[t];
    const float ce_r = g_lse_row[t] - diag;
    const float ce_c = lse_col - diag;
    const float u = g_u[t];
    const float as = 0.5f * (g_ms1[t] + g_ms2[t]);
    float v[6] = { ce_r, ce_c, u, u * u, as * as, u * as };
    const int lane = t & 31, w = t >> 5;
#pragma unroll
    for (int k = 0; k < 6; k++) {
        const float r = wsum(v[k]);
        if (!lane) sh[k][w] = r;
    }
    __syncthreads();
    if (t == 0) {
        float s[6];
        for (int k = 0; k < 6; k++) {
            float a = 0.f;
            for (int q = 0; q < 16; q++) a += sh[k][q];
            s[k] = a;
        }
        const float loss_pro = 0.5f * ((s[0] + s[1]) * (1.0f / NB));
        const float cosv = s[5] / (fmaxf(sqrtf(s[3]), 1e-12f) * fmaxf(sqrtf(s[4]), 1e-12f));
        out[0] = loss_pro;
        out[1] = 2.4f * (1.0f - cosv);
        out[2] = 0.5f * (s[2] * (1.0f / NB));
    }
}

// ---------------- launch ----------------
extern "C" void kernel_launch(void* const* d_in, const int* in_sizes, int n_in,
                              void* d_out, int out_size)
{
    const float* mu1 = (const float*)d_in[0];
    const float* s1  = (const float*)d_in[1];
    const float* mu2 = (const float*)d_in[2];
    const float* s2  = (const float*)d_in[3];
    const float* ls  = (const float*)d_in[4];
    float* out = (float*)d_out;

    prep_kernel<<<2 * NB, 256>>>(mu1, s1, mu2, s2);
    dim3 grid(NB / 32, NB / 32);
    bd_kernel<<<grid, 128>>>(s1, s2);
    rowcol_kernel<<<NB + 256, 256>>>(ls);
    final_kernel<<<1, NB>>>(out);
}

// round 6
// speedup vs baseline: 1.6430x; 1.1217x over previous
#include <cuda_runtime.h>
#include <math.h>

#define NB 512
#define ND 512
#define EPSF 1e-6f
#define HEPS (0.5f*1e-6f)

typedef unsigned long long u64t;

// ---------------- f32x2 packed helpers (sm_100a) ----------------
__device__ __forceinline__ u64t pk2(float lo, float hi){ u64t r; asm("mov.b64 %0, {%1,%2};" : "=l"(r) : "f"(lo), "f"(hi)); return r; }
__device__ __forceinline__ void upk2(u64t v, float&lo, float&hi){ asm("mov.b64 {%0,%1}, %2;" : "=f"(lo), "=f"(hi) : "l"(v)); }
__device__ __forceinline__ u64t fma2_(u64t a,u64t b,u64t c){ u64t d; asm("fma.rn.f32x2 %0,%1,%2,%3;" : "=l"(d) : "l"(a),"l"(b),"l"(c)); return d; }
__device__ __forceinline__ u64t mul2_(u64t a,u64t b){ u64t d; asm("mul.rn.f32x2 %0,%1,%2;" : "=l"(d) : "l"(a),"l"(b)); return d; }
__device__ __forceinline__ u64t add2_(u64t a,u64t b){ u64t d; asm("add.rn.f32x2 %0,%1,%2;" : "=l"(d) : "l"(a),"l"(b)); return d; }
__device__ __forceinline__ float rcpa(float x){ float r; asm("rcp.approx.f32 %0, %1;" : "=f"(r) : "f"(x)); return r; }
__device__ __forceinline__ float lg2a(float x){ float r; asm("lg2.approx.f32 %0, %1;" : "=f"(r) : "f"(x)); return r; }

// ---------------- scratch ----------------
__device__ float g_n1[NB * ND];
__device__ float g_n2[NB * ND];   // NEGATED normalized mu2
__device__ float g_h1[NB * ND];   // 0.5*sigma1 + HEPS
__device__ float g_h2[NB * ND];   // 0.5*sigma2 + HEPS
__device__ float g_sim[NB * NB];
__device__ float g_sim2[NB * NB];
__device__ float g_ld1[NB], g_ld2[NB];
__device__ float g_ms1[NB], g_ms2[NB];
__device__ float g_lse_row[NB], g_diagl[NB], g_u[NB];
__device__ float g_cm[8 * NB], g_cs[8 * NB];

// ---------------- reduction helpers ----------------
__device__ __forceinline__ float wsum(float v) {
#pragma unroll
    for (int o = 16; o; o >>= 1) v += __shfl_down_sync(0xffffffffu, v, o);
    return v;
}
__device__ __forceinline__ float wmax(float v) {
#pragma unroll
    for (int o = 16; o; o >>= 1) v = fmaxf(v, __shfl_down_sync(0xffffffffu, v, o));
    return v;
}

// ---------------- kernel 1: per-row normalize + stats + halved sigma ----------------
__global__ void prep_kernel(const float* __restrict__ mu1, const float* __restrict__ s1,
                            const float* __restrict__ mu2, const float* __restrict__ s2)
{
    __shared__ float sh[3][8];
    __shared__ float s_inv;
    const int row = blockIdx.x;
    const bool first = row < NB;
    const int r = first ? row : row - NB;
    const float* mu = (first ? mu1 : mu2) + r * ND;
    const float* sg = (first ? s1 : s2) + r * ND;
    float* nout = (first ? g_n1 : g_n2) + r * ND;
    float* hout = (first ? g_h1 : g_h2) + r * ND;
    const int t = threadIdx.x;

    float ssq = 0.f, lsum = 0.f, msum = 0.f;
    for (int c = t; c < ND; c += 256) {
        float x = mu[c];
        ssq += x * x;
        float sv = sg[c];
        lsum += __logf(sv + EPSF);
        msum += sv;
        hout[c] = fmaf(0.5f, sv, HEPS);
    }
    ssq = wsum(ssq); lsum = wsum(lsum); msum = wsum(msum);
    const int lane = t & 31, w = t >> 5;
    if (!lane) { sh[0][w] = ssq; sh[1][w] = lsum; sh[2][w] = msum; }
    __syncthreads();
    if (t == 0) {
        float a = 0.f, b = 0.f, c2 = 0.f;
        for (int k = 0; k < 8; k++) { a += sh[0][k]; b += sh[1][k]; c2 += sh[2][k]; }
        float inv = 1.0f / fmaxf(sqrtf(a), 1e-12f);
        s_inv = first ? inv : -inv;          // negate n2 once here
        (first ? g_ld1 : g_ld2)[r] = b;
        (first ? g_ms1 : g_ms2)[r] = c2 * (1.0f / ND);
    }
    __syncthreads();
    const float inv = s_inv;
    for (int c = t; c < ND; c += 256) nout[c] = mu[c] * inv;
}

// ---------------- kernel 2: Bhattacharyya O(B^2 D) pass ----------------
// 32x32 output tile, 256 threads = 2 groups of 128 splitting D.
// Warps 0-3 are group 0, warps 4-7 group 1 -> every SMSP hosts one warp of
// EACH group, so one group's load phase overlaps the other group's FMA phase.
// Microtile 4i x 2j (j packed as one f32x2), 12 u64 accumulators.
__global__ void __launch_bounds__(256, 2) bd_kernel()
{
    __shared__ __align__(16) float sn1[2][32][36], ss1[2][32][36];   // [grp][row i][d]
    __shared__ __align__(16) float sn2[2][32][34], ss2[2][32][34];   // [grp][d][row j]
    __shared__ u64t comb[128][12];                                   // group-1 partials

    const int bi = blockIdx.y * 32, bj = blockIdx.x * 32;
    const int tid = threadIdx.x;
    const int g  = tid >> 7;          // group id 0/1 (warps 0-3 vs 4-7)
    const int t  = tid & 127;         // thread-in-group
    const int tx = t & 15, ty = t >> 4;
    const int i0 = ty * 4, j0 = tx * 2;
    const int lc = t & 31, lw = t >> 5;   // loader: 4 warps x 8 rows

    u64t t1a[4], d2a[4], lda[4];
#pragma unroll
    for (int x = 0; x < 4; x++) { t1a[x] = 0ull; d2a[x] = 0ull; lda[x] = 0ull; }

    for (int dc = g * 32; dc < ND; dc += 64) {
#pragma unroll
        for (int k = 0; k < 8; k++) {
            const int r = lw * 8 + k;
            sn1[g][r][lc] = g_n1[(bi + r) * ND + dc + lc];
            ss1[g][r][lc] = g_h1[(bi + r) * ND + dc + lc];
            sn2[g][lc][r] = g_n2[(bj + r) * ND + dc + lc];   // already negated
            ss2[g][lc][r] = g_h2[(bj + r) * ND + dc + lc];
        }
        asm volatile("bar.sync %0, 128;" :: "r"(g + 1) : "memory");

#pragma unroll 2
        for (int dg = 0; dg < 32; dg += 4) {
            u64t bn[4], q[4];
#pragma unroll
            for (int dd = 0; dd < 4; dd++) {
                bn[dd] = *(const u64t*)&sn2[g][dg + dd][j0];
                q[dd]  = *(const u64t*)&ss2[g][dg + dd][j0];
            }
#pragma unroll
            for (int x = 0; x < 4; x++) {
                const float4 av = *(const float4*)&sn1[g][i0 + x][dg];
                const float4 pv = *(const float4*)&ss1[g][i0 + x][dg];
                const u64t s0  = add2_(pk2(pv.x, pv.x), q[0]);
                const u64t s1_ = add2_(pk2(pv.y, pv.y), q[1]);
                const u64t s2_ = add2_(pk2(pv.z, pv.z), q[2]);
                const u64t s3_ = add2_(pk2(pv.w, pv.w), q[3]);
                const u64t df0 = add2_(pk2(av.x, av.x), bn[0]);   // a - b (b negated)
                const u64t df1 = add2_(pk2(av.y, av.y), bn[1]);
                const u64t df2 = add2_(pk2(av.z, av.z), bn[2]);
                const u64t df3 = add2_(pk2(av.w, av.w), bn[3]);
                const u64t sq0 = mul2_(df0, df0);
                const u64t sq1 = mul2_(df1, df1);
                const u64t sq2 = mul2_(df2, df2);
                const u64t sq3 = mul2_(df3, df3);
                d2a[x] = add2_(d2a[x], add2_(add2_(sq0, sq1), add2_(sq2, sq3)));
                // batched product for log + Montgomery batch inversion (group of 4)
                const u64t p01  = mul2_(s0, s1_);
                const u64t p012 = mul2_(p01, s2_);
                const u64t P    = mul2_(p012, s3_);
                float Pl, Ph; upk2(P, Pl, Ph);
                lda[x] = add2_(lda[x], pk2(lg2a(Pl), lg2a(Ph)));
                const u64t r2   = pk2(rcpa(Pl), rcpa(Ph));
                const u64t inv3 = mul2_(r2, p012);
                const u64t r3   = mul2_(r2, s3_);
                const u64t inv2 = mul2_(r3, p01);
                const u64t r23  = mul2_(r3, s2_);
                const u64t inv1 = mul2_(r23, s0);
                const u64t inv0 = mul2_(r23, s1_);
                t1a[x] = fma2_(sq0, inv0, t1a[x]);
                t1a[x] = fma2_(sq1, inv1, t1a[x]);
                t1a[x] = fma2_(sq2, inv2, t1a[x]);
                t1a[x] = fma2_(sq3, inv3, t1a[x]);
            }
        }
        asm volatile("bar.sync %0, 128;" :: "r"(g + 1) : "memory");
    }

    // ---- combine group partials: group 1 -> smem, group 0 adds + epilogue ----
    if (g == 1) {
#pragma unroll
        for (int x = 0; x < 4; x++) {
            comb[t][3 * x]     = t1a[x];
            comb[t][3 * x + 1] = d2a[x];
            comb[t][3 * x + 2] = lda[x];
        }
    }
    __syncthreads();
    if (g == 0) {
#pragma unroll
        for (int x = 0; x < 4; x++) {
            t1a[x] = add2_(t1a[x], comb[t][3 * x]);
            d2a[x] = add2_(d2a[x], comb[t][3 * x + 1]);
            lda[x] = add2_(lda[x], comb[t][3 * x + 2]);
        }
        const int j = bj + j0;
        const float ld2A = g_ld2[j], ld2B = g_ld2[j + 1];
#pragma unroll
        for (int x = 0; x < 4; x++) {
            const int i = bi + i0 + x;
            const float ld1v = g_ld1[i];
            float tA, tB, dA, dB, lA, lB;
            upk2(t1a[x], tA, tB);
            upk2(d2a[x], dA, dB);
            upk2(lda[x], lA, lB);
            const float t2A = lA * (float)M_LN2 - 0.5f * (ld1v + ld2A);
            const float t2B = lB * (float)M_LN2 - 0.5f * (ld1v + ld2B);
            const float bdA = fmaf(0.125f, tA, 0.5f * t2A);
            const float bdB = fmaf(0.125f, tB, 0.5f * t2B);
            *(float2*)&g_sim[i * NB + j]  = make_float2(__expf(-bdA * (1.0f / ND)),
                                                        __expf(-bdB * (1.0f / ND)));
            *(float2*)&g_sim2[i * NB + j] = make_float2(__expf(-dA), __expf(-dB));
        }
    }
}

// ---------------- kernel 3: fused row LSE + column LSE partials ----------------
// blocks [0,NB): per-row LSE + uncertainty.  blocks [NB, NB+128): column partials
// over 64-row stripes (8 stripes x 16 col-groups).
__global__ void rowcol_kernel(const float* __restrict__ lsp)
{
    const float scale = lsp[0];
    const int t = threadIdx.x;
    const int lane = t & 31, w = t >> 5;

    if (blockIdx.x < NB) {
        __shared__ float shm[8], shm2[8], shs[8];
        __shared__ float s_diag, s_diag2, s_M, s_M2;
        const int i = blockIdx.x;
        const float* simr = g_sim + i * NB;
        const float* sim2r = g_sim2 + i * NB;

        const float l0 = scale * simr[t], l1 = scale * simr[t + 256];
        const float v0 = sim2r[t],        v1 = sim2r[t + 256];
        float m = fmaxf(l0, l1);
        float m2 = -1.0f;
        if (t == i)       { s_diag = l0; s_diag2 = v0; } else m2 = v0;
        if (t + 256 == i) { s_diag = l1; s_diag2 = v1; } else m2 = fmaxf(m2, v1);

        m = wmax(m); m2 = wmax(m2);
        if (!lane) { shm[w] = m; shm2[w] = m2; }
        __syncthreads();
        if (t == 0) {
            float M = shm[0], M2 = shm2[0];
            for (int k = 1; k < 8; k++) { M = fmaxf(M, shm[k]); M2 = fmaxf(M2, shm2[k]); }
            s_M = M; s_M2 = M2;
        }
        __syncthreads();
        const float M = s_M;
        float su = __expf(l0 - M) + __expf(l1 - M);
        su = wsum(su);
        if (!lane) shs[w] = su;
        __syncthreads();
        if (t == 0) {
            float S = 0.f;
            for (int k = 0; k < 8; k++) S += shs[k];
            g_lse_row[i] = M + __logf(S);
            g_diagl[i]   = s_diag;
            g_u[i]       = __expf(-s_diag2 / s_M2);
        }
    } else {
        __shared__ float sm[8][32], ssp[8][32];
        const int bid = blockIdx.x - NB;
        const int jg = bid & 15, rg = bid >> 4;      // 16 col-groups x 8 row-stripes
        const int x = t & 31, y = t >> 5;
        const int j = jg * 32 + x;
        const int r0 = rg * 64 + y * 8;
        float m = -1e30f, s = 0.0f;
#pragma unroll
        for (int k = 0; k < 8; k++) {
            const float l = scale * g_sim[(r0 + k) * NB + j];
            const float nm = fmaxf(m, l);
            s = s * __expf(m - nm) + __expf(l - nm);
            m = nm;
        }
        sm[y][x] = m; ssp[y][x] = s;
        __syncthreads();
        if (y == 0) {
            float M = m;
#pragma unroll
            for (int k = 1; k < 8; k++) M = fmaxf(M, sm[k][x]);
            float S = 0.f;
#pragma unroll
            for (int k = 0; k < 8; k++) S += ssp[k][x] * __expf(sm[k][x] - M);
            g_cm[rg * NB + j] = M;
            g_cs[rg * NB + j] = S;
        }
    }
}

// ---------------- kernel 4: final reductions (incl. column LSE combine) ----------------
__global__ void final_kernel(float* __restrict__ out)
{
    __shared__ float sh[6][16];
    const int t = threadIdx.x;   // 512 threads
    float M = -1e30f;
#pragma unroll
    for (int k = 0; k < 8; k++) M = fmaxf(M, g_cm[k * NB + t]);
    float S = 0.f;
#pragma unroll
    for (int k = 0; k < 8; k++) S += g_cs[k * NB + t] * __expf(g_cm[k * NB + t] - M);
    const float lse_col = M + __logf(S);

    const float diag = g_diagl[t];
    const float ce_r = g_lse_row[t] - diag;
    const float ce_c = lse_col - diag;
    const float u = g_u[t];
    const float as = 0.5f * (g_ms1[t] + g_ms2[t]);
    float v[6] = { ce_r, ce_c, u, u * u, as * as, u * as };
    const int lane = t & 31, w = t >> 5;
#pragma unroll
    for (int k = 0; k < 6; k++) {
        const float r = wsum(v[k]);
        if (!lane) sh[k][w] = r;
    }
    __syncthreads();
    if (t == 0) {
        float s[6];
        for (int k = 0; k < 6; k++) {
            float a = 0.f;
            for (int q = 0; q < 16; q++) a += sh[k][q];
            s[k] = a;
        }
        const float loss_pro = 0.5f * ((s[0] + s[1]) * (1.0f / NB));
        const float cosv = s[5] / (fmaxf(sqrtf(s[3]), 1e-12f) * fmaxf(sqrtf(s[4]), 1e-12f));
        out[0] = loss_pro;
        out[1] = 2.4f * (1.0f - cosv);
        out[2] = 0.5f * (s[2] * (1.0f / NB));
    }
}

// ---------------- launch ----------------
extern "C" void kernel_launch(void* const* d_in, const int* in_sizes, int n_in,
                              void* d_out, int out_size)
{
    const float* mu1 = (const float*)d_in[0];
    const float* s1  = (const float*)d_in[1];
    const float* mu2 = (const float*)d_in[2];
    const float* s2  = (const float*)d_in[3];
    const float* ls  = (const float*)d_in[4];
    float* out = (float*)d_out;

    prep_kernel<<<2 * NB, 256>>>(mu1, s1, mu2, s2);
    dim3 grid(NB / 32, NB / 32);
    bd_kernel<<<grid, 256>>>();
    rowcol_kernel<<<NB + 128, 256>>>(ls);
    final_kernel<<<1, NB>>>(out);
}